// round 3
// baseline (speedup 1.0000x reference)
#include <cuda_runtime.h>
#include <cstdint>

#define Npts   20000
#define Msamp  5000
#define KNN    16
#define CIN    64
#define COUT   128
#define FDIM   (3 + CIN)          // 67
#define BN_EPS 1e-5f

// FPS parallelization
#define FPS_CTAS    32
#define FPS_THREADS 256
#define FPS_WARPS   (FPS_THREADS / 32)
#define FPS_SLOTS   (FPS_CTAS * FPS_WARPS)   // 256
#define PPC         (Npts / FPS_CTAS)        // 625 points per CTA
#define PPT         3                         // ceil(625/256)

// ---------------- device scratch (no allocs allowed) ----------------
__device__ float4 g_p4[Npts];          // x,y,z, |p|^2
__device__ float4 g_q4[Msamp];         // sampled q + |q|^2
__device__ int    g_nidx[Msamp * KNN];
__device__ float  g_h[Msamp * KNN * COUT];   // ~41 MB pre-BN activations
__device__ float  g_ps [Msamp * COUT];
__device__ float  g_pss[Msamp * COUT];
__device__ float  g_mean[COUT];
__device__ float  g_rstd[COUT];
__device__ float  g_np_scratch[Msamp * 3];
// double-buffered tagged argmax partials (tag in same 64-bit word -> no fences)
__device__ volatile unsigned long long g_part[2][FPS_SLOTS];

// ---------------- pack: p [N,3] -> float4 with |p|^2 ----------------
__global__ void pack_kernel(const float* __restrict__ p) {
    int i = blockIdx.x * blockDim.x + threadIdx.x;
    if (i < Npts) {
        float x = p[3 * i], y = p[3 * i + 1], z = p[3 * i + 2];
        float pp = __fadd_rn(__fadd_rn(__fmul_rn(x, x), __fmul_rn(y, y)), __fmul_rn(z, z));
        g_p4[i] = make_float4(x, y, z, pp);
    }
}

// ---------------- FPS: 32 CTAs, lock-free tagged gmem reduction ----------------
// Same arithmetic + argmax key law as the verified bit-exact single-block version.
__global__ __launch_bounds__(FPS_THREADS, 1) void fps_multi_kernel(float* __restrict__ out_np) {
    const int cta  = blockIdx.x;
    const int t    = threadIdx.x;
    const int warp = t >> 5, lane = t & 31;
    const int base = cta * PPC;

    // register-resident slice: coords + running dist
    float px[PPT], py[PPT], pz[PPT], dist[PPT];
    int   gidx[PPT];
    bool  valid[PPT];
#pragma unroll
    for (int j = 0; j < PPT; j++) {
        int li = t + j * FPS_THREADS;
        valid[j] = (li < PPC);
        gidx[j]  = base + li;
        float4 P = g_p4[valid[j] ? gidx[j] : base];
        px[j] = P.x; py[j] = P.y; pz[j] = P.z;
        dist[j] = 1e10f;
    }

    float lx, ly, lz;
    {
        float4 P0 = g_p4[0];
        lx = P0.x; ly = P0.y; lz = P0.z;
        if (cta == 0 && t == 0) {
            out_np[0] = P0.x; out_np[1] = P0.y; out_np[2] = P0.z;
            g_q4[0] = P0;
        }
    }

    for (int i = 1; i < Msamp; i++) {
        // --- update dists, thread-local best key ---
        unsigned long long best = 0;
#pragma unroll
        for (int j = 0; j < PPT; j++) {
            float dx = __fsub_rn(px[j], lx);
            float dy = __fsub_rn(py[j], ly);
            float dz = __fsub_rn(pz[j], lz);
            float d  = __fadd_rn(__fadd_rn(__fmul_rn(dx, dx), __fmul_rn(dy, dy)),
                                 __fmul_rn(dz, dz));
            float nd = fminf(dist[j], d);
            dist[j] = nd;
            if (valid[j]) {
                unsigned long long k =
                    ((unsigned long long)__float_as_uint(nd) << 15) |
                    (unsigned)(32767 - gidx[j]);
                if (k > best) best = k;
            }
        }
        // --- warp-local reduce (lane 0 gets max key) ---
#pragma unroll
        for (int off = 16; off; off >>= 1) {
            unsigned long long o = __shfl_down_sync(0xFFFFFFFFu, best, off);
            if (o > best) best = o;
        }
        const int buf = i & 1;
        if (lane == 0)
            g_part[buf][cta * FPS_WARPS + warp] =
                best | ((unsigned long long)i << 47);

        // --- spin-poll all 256 slots (8 per lane), reduce redundantly ---
        const unsigned long long tag = (unsigned long long)i;
        unsigned long long w;
        for (;;) {
            unsigned long long v[8];
            bool ok = true;
#pragma unroll
            for (int r = 0; r < 8; r++) {
                v[r] = g_part[buf][lane + 32 * r];
                ok &= ((v[r] >> 47) == tag);
            }
            if (__all_sync(0xFFFFFFFFu, ok)) {
                unsigned long long m = v[0];
#pragma unroll
                for (int r = 1; r < 8; r++) if (v[r] > m) m = v[r];
#pragma unroll
                for (int off = 16; off; off >>= 1) {
                    unsigned long long o = __shfl_xor_sync(0xFFFFFFFFu, m, off);
                    if (o > m) m = o;
                }
                w = m;
                break;
            }
        }
        const int widx = 32767 - (int)(w & 0x7FFFull);
        float4 P = g_p4[widx];               // same address warp-wide -> broadcast
        lx = P.x; ly = P.y; lz = P.z;
        if (cta == 0 && t == 0) {
            out_np[3 * i] = P.x; out_np[3 * i + 1] = P.y; out_np[3 * i + 2] = P.z;
            g_q4[i] = P;
        }
    }
}

// ---------------- kNN: warp per query, threshold + ballot buffer ----------------
#define INFKEY 0xFFFFFFFFFFFFFFFFull

__device__ __forceinline__ void knn_merge(unsigned long long* cand, int lane,
                                          unsigned long long& cur,
                                          unsigned long long& thr, int& cnt) {
    if (lane < 16) cand[64 + lane] = cur;
#pragma unroll
    for (int s = lane; s < 64; s += 32) if (s >= cnt) cand[s] = INFKEY;
    __syncwarp();
    unsigned long long picked = INFKEY, last = INFKEY;
#pragma unroll 1
    for (int r = 0; r < 16; r++) {
        unsigned long long a = cand[lane];
        unsigned long long b = cand[lane + 32];
        unsigned long long c = (lane < 16) ? cand[64 + lane] : INFKEY;
        unsigned long long v = a < b ? a : b;
        v = v < c ? v : c;
#pragma unroll
        for (int off = 16; off; off >>= 1) {
            unsigned long long o = __shfl_down_sync(0xFFFFFFFFu, v, off);
            if (o < v) v = o;
        }
        v = __shfl_sync(0xFFFFFFFFu, v, 0);
        if (a == v)                       cand[lane]      = INFKEY;
        else if (b == v)                  cand[lane + 32] = INFKEY;
        else if (lane < 16 && c == v)     cand[64 + lane] = INFKEY;
        __syncwarp();
        if (lane == r) picked = v;
        last = v;
    }
    cur = picked; thr = last; cnt = 0;
    __syncwarp();
}

__global__ __launch_bounds__(128) void knn_kernel() {
    __shared__ unsigned long long cand_s[4][80];
    const int warp = threadIdx.x >> 5, lane = threadIdx.x & 31;
    const int m = blockIdx.x * 4 + warp;
    unsigned long long* cand = cand_s[warp];

    const float4 Q = g_q4[m];
    unsigned long long cur = INFKEY, thr = INFKEY;
    int cnt = 0;

#pragma unroll 1
    for (int s = 0; s < Npts / 32; s++) {
        int idx = lane + 32 * s;
        float4 P = __ldg(&g_p4[idx]);
        // reference: qq - 2*(q@p.T) + pp, dot as XLA fma chain
        float dot = __fmaf_rn(Q.z, P.z, __fmaf_rn(Q.y, P.y, __fmul_rn(Q.x, P.x)));
        float d = __fadd_rn(__fsub_rn(Q.w, __fmul_rn(2.0f, dot)), P.w);
        unsigned ub = __float_as_uint(d);
        ub ^= (ub >> 31) ? 0xFFFFFFFFu : 0x80000000u;
        unsigned long long k = ((unsigned long long)ub << 32) | (unsigned)idx;
        bool pred = k < thr;
        unsigned bal = __ballot_sync(0xFFFFFFFFu, pred);
        if (pred) {
            int pos = cnt + __popc(bal & ((1u << lane) - 1u));
            cand[pos] = k;
        }
        cnt += __popc(bal);
        if (cnt >= 32) knn_merge(cand, lane, cur, thr, cnt);
    }
    if (cnt > 0) knn_merge(cand, lane, cur, thr, cnt);
    if (lane < 16) g_nidx[m * KNN + lane] = (int)(unsigned)(cur & 0xFFFFFFFFull);
}

// ---------------- gather + linear (feat @ W), stash h + partial BN sums ----------------
__global__ __launch_bounds__(128) void gemm_kernel(const float* __restrict__ x,
                                                   const float* __restrict__ W) {
    __shared__ float sW[FDIM * COUT];
    __shared__ float sF[KNN][FDIM + 1];
    const int m = blockIdx.x, t = threadIdx.x;

    for (int i = t; i < FDIM * COUT; i += 128) sW[i] = W[i];
    const float4 Q = g_q4[m];
    for (int e = t; e < KNN * FDIM; e += 128) {
        int r = e / FDIM, j = e - r * FDIM;
        int n = g_nidx[m * KNN + r];
        float v;
        if (j < 3) {
            float4 P = g_p4[n];
            v = (j == 0) ? __fsub_rn(P.x, Q.x) : (j == 1) ? __fsub_rn(P.y, Q.y)
                                                          : __fsub_rn(P.z, Q.z);
        } else {
            v = __ldg(&x[n * CIN + (j - 3)]);
        }
        sF[r][j] = v;
    }
    __syncthreads();

    float acc[KNN];
#pragma unroll
    for (int r = 0; r < KNN; r++) acc[r] = 0.0f;
#pragma unroll 1
    for (int j = 0; j < FDIM; j++) {
        float wv = sW[j * COUT + t];
#pragma unroll
        for (int r = 0; r < KNN; r++) acc[r] = fmaf(sF[r][j], wv, acc[r]);
    }
    float s1 = 0.0f, s2 = 0.0f;
#pragma unroll
    for (int r = 0; r < KNN; r++) {
        g_h[(m * KNN + r) * COUT + t] = acc[r];
        s1 += acc[r];
        s2 = fmaf(acc[r], acc[r], s2);
    }
    g_ps [m * COUT + t] = s1;
    g_pss[m * COUT + t] = s2;
}

// ---------------- deterministic BN stats reduction ----------------
__global__ __launch_bounds__(256) void stats_kernel() {
    __shared__ float s1[256], s2[256];
    const int c = blockIdx.x, t = threadIdx.x;
    float a = 0.0f, b = 0.0f;
    for (int m = t; m < Msamp; m += 256) {
        a += g_ps [m * COUT + c];
        b += g_pss[m * COUT + c];
    }
    s1[t] = a; s2[t] = b;
    __syncthreads();
    for (int o = 128; o; o >>= 1) {
        if (t < o) { s1[t] += s1[t + o]; s2[t] += s2[t + o]; }
        __syncthreads();
    }
    if (t == 0) {
        const float inv_n = 1.0f / (float)(Msamp * KNN);
        float mean = s1[0] * inv_n;
        float var  = fmaxf(s2[0] * inv_n - mean * mean, 0.0f);
        g_mean[c] = mean;
        g_rstd[c] = rsqrtf(var + BN_EPS);
    }
}

// ---------------- BN + ReLU + maxpool over k ----------------
__global__ __launch_bounds__(128) void final_kernel(const float* __restrict__ gamma,
                                                    const float* __restrict__ beta,
                                                    float* __restrict__ out_x,
                                                    float* __restrict__ out_no) {
    const int m = blockIdx.x, c = threadIdx.x;
    const float mean = g_mean[c], inv = g_rstd[c];
    const float gm = __ldg(&gamma[c]), bt = __ldg(&beta[c]);
    float mx = 0.0f;
#pragma unroll
    for (int r = 0; r < KNN; r++) {
        float h = g_h[(m * KNN + r) * COUT + c];
        float y = (h - mean) * inv * gm + bt;
        y = fmaxf(y, 0.0f);
        mx = fmaxf(mx, y);
    }
    out_x[m * COUT + c] = mx;
    if (out_no != nullptr && m == 0 && c == 0) *out_no = (float)Msamp;
}

// ---------------- launch ----------------
extern "C" void kernel_launch(void* const* d_in, const int* in_sizes, int n_in,
                              void* d_out, int out_size) {
    const float* p     = (const float*)d_in[0];
    const float* x     = (const float*)d_in[1];
    const float* W     = (const float*)d_in[3];
    const float* gamma = (const float*)d_in[4];
    const float* beta  = (const float*)d_in[5];
    float* out = (float*)d_out;

    const int np_elems = Msamp * 3;
    const int x_elems  = Msamp * COUT;

    float* np_dst = out;
    float* x_dst  = out + np_elems;
    float* no_dst = nullptr;
    if (out_size >= np_elems + x_elems + 1) {
        no_dst = out + np_elems + x_elems;
    } else if (out_size == x_elems) {
        float* scr; cudaGetSymbolAddress((void**)&scr, g_np_scratch);
        np_dst = scr;
        x_dst  = out;
    }

    pack_kernel     <<<(Npts + 255) / 256, 256>>>(p);
    fps_multi_kernel<<<FPS_CTAS, FPS_THREADS>>>(np_dst);
    knn_kernel      <<<Msamp / 4, 128>>>();
    gemm_kernel     <<<Msamp, 128>>>(x, W);
    stats_kernel    <<<COUT, 256>>>();
    final_kernel    <<<Msamp, 128>>>(gamma, beta, x_dst, no_dst);
}

// round 4
// speedup vs baseline: 3.0186x; 3.0186x over previous
#include <cuda_runtime.h>
#include <cstdint>

#define Npts   20000
#define Msamp  5000
#define KNN    16
#define CIN    64
#define COUT   128
#define FDIM   (3 + CIN)          // 67
#define BN_EPS 1e-5f

// FPS parallelization
#define FPS_CTAS    32
#define FPS_THREADS 128
#define FPS_WARPS   (FPS_THREADS / 32)       // 4
#define PPC         (Npts / FPS_CTAS)        // 625 points per CTA
#define PPT         5                         // ceil(625/128)

// ---------------- device scratch (no allocs allowed) ----------------
__device__ float4 g_p4[Npts];          // x,y,z, |p|^2
__device__ float4 g_q4[Msamp];         // sampled q + |q|^2
__device__ int    g_nidx[Msamp * KNN];
__device__ float  g_h[Msamp * KNN * COUT];   // pre-BN activations
__device__ float  g_ps [Msamp * COUT];
__device__ float  g_pss[Msamp * COUT];
__device__ float  g_mean[COUT];
__device__ float  g_rstd[COUT];
__device__ float  g_np_scratch[Msamp * 3];
// double-buffered tagged per-CTA argmax partials, 128B padded (one L2 line each)
__device__ volatile unsigned long long g_slot[2][FPS_CTAS][16];

// ---------------- pack: p [N,3] -> float4 with |p|^2 ----------------
__global__ void pack_kernel(const float* __restrict__ p) {
    int i = blockIdx.x * blockDim.x + threadIdx.x;
    if (i < Npts) {
        float x = p[3 * i], y = p[3 * i + 1], z = p[3 * i + 2];
        float pp = __fadd_rn(__fadd_rn(__fmul_rn(x, x), __fmul_rn(y, y)), __fmul_rn(z, z));
        g_p4[i] = make_float4(x, y, z, pp);
    }
}

// ---------------- FPS: 32 CTAs, leader-warp poll of 32 padded slots ----------------
// Arithmetic + argmax key law identical to the verified bit-exact versions.
__global__ __launch_bounds__(FPS_THREADS, 1) void fps_multi_kernel(float* __restrict__ out_np) {
    const int cta  = blockIdx.x;
    const int t    = threadIdx.x;
    const int warp = t >> 5, lane = t & 31;
    const int base = cta * PPC;

    float px[PPT], py[PPT], pz[PPT], dist[PPT];
    unsigned keylo[PPT];
    bool valid[PPT];
#pragma unroll
    for (int j = 0; j < PPT; j++) {
        int li = t + j * FPS_THREADS;
        valid[j] = (li < PPC);
        int gi = base + (valid[j] ? li : 0);
        float4 P = g_p4[gi];
        px[j] = P.x; py[j] = P.y; pz[j] = P.z;
        dist[j] = 1e10f;
        keylo[j] = (unsigned)(32767 - gi);
    }

    __shared__ unsigned long long s_warp[FPS_WARPS];
    __shared__ float4 s_last;

    float lx, ly, lz;
    {
        float4 P0 = g_p4[0];
        lx = P0.x; ly = P0.y; lz = P0.z;
        if (cta == 0 && t == 0) {
            out_np[0] = P0.x; out_np[1] = P0.y; out_np[2] = P0.z;
            g_q4[0] = P0;
        }
    }

    for (int i = 1; i < Msamp; i++) {
        // --- update dists, thread-local best key ---
        unsigned long long best = 0;
#pragma unroll
        for (int j = 0; j < PPT; j++) {
            float dx = __fsub_rn(px[j], lx);
            float dy = __fsub_rn(py[j], ly);
            float dz = __fsub_rn(pz[j], lz);
            float d  = __fadd_rn(__fadd_rn(__fmul_rn(dx, dx), __fmul_rn(dy, dy)),
                                 __fmul_rn(dz, dz));
            float nd = fminf(dist[j], d);
            dist[j] = nd;
            unsigned long long k =
                ((unsigned long long)__float_as_uint(nd) << 15) | keylo[j];
            if (valid[j] && k > best) best = k;
        }
        // --- warp reduce (max) ---
#pragma unroll
        for (int off = 16; off; off >>= 1) {
            unsigned long long o = __shfl_down_sync(0xFFFFFFFFu, best, off);
            if (o > best) best = o;
        }
        if (lane == 0) s_warp[warp] = best;
        __syncthreads();

        if (warp == 0) {
            // cross-warp reduce (4 partials)
            unsigned long long b = (lane < FPS_WARPS) ? s_warp[lane] : 0;
#pragma unroll
            for (int off = 2; off; off >>= 1) {
                unsigned long long o = __shfl_down_sync(0xFFFFFFFFu, b, off);
                if (o > b) b = o;
            }
            b = __shfl_sync(0xFFFFFFFFu, b, 0);
            const int buf = i & 1;
            if (lane == 0)
                g_slot[buf][cta][0] = b | ((unsigned long long)i << 47);

            // poll: one slot per lane, all 32 CTAs
            const unsigned long long want = (unsigned long long)i;
            unsigned long long v;
            do {
                v = g_slot[buf][lane][0];
            } while (!__all_sync(0xFFFFFFFFu, (v >> 47) == want));
            // global max reduce
#pragma unroll
            for (int off = 16; off; off >>= 1) {
                unsigned long long o = __shfl_xor_sync(0xFFFFFFFFu, v, off);
                if (o > v) v = o;
            }
            if (lane == 0) {
                int widx = 32767 - (int)(v & 0x7FFFull);
                float4 P = g_p4[widx];
                s_last = P;
                if (cta == 0) {
                    out_np[3 * i] = P.x; out_np[3 * i + 1] = P.y; out_np[3 * i + 2] = P.z;
                    g_q4[i] = P;
                }
            }
        }
        __syncthreads();
        lx = s_last.x; ly = s_last.y; lz = s_last.z;
    }
}

// ---------------- kNN: warp per query, threshold + ballot buffer ----------------
#define INFKEY 0xFFFFFFFFFFFFFFFFull

__device__ __forceinline__ void knn_merge(unsigned long long* cand, int lane,
                                          unsigned long long& cur,
                                          unsigned long long& thr, int& cnt) {
    if (lane < 16) cand[64 + lane] = cur;
#pragma unroll
    for (int s = lane; s < 64; s += 32) if (s >= cnt) cand[s] = INFKEY;
    __syncwarp();
    unsigned long long picked = INFKEY, last = INFKEY;
#pragma unroll 1
    for (int r = 0; r < 16; r++) {
        unsigned long long a = cand[lane];
        unsigned long long b = cand[lane + 32];
        unsigned long long c = (lane < 16) ? cand[64 + lane] : INFKEY;
        unsigned long long v = a < b ? a : b;
        v = v < c ? v : c;
#pragma unroll
        for (int off = 16; off; off >>= 1) {
            unsigned long long o = __shfl_down_sync(0xFFFFFFFFu, v, off);
            if (o < v) v = o;
        }
        v = __shfl_sync(0xFFFFFFFFu, v, 0);
        if (a == v)                       cand[lane]      = INFKEY;
        else if (b == v)                  cand[lane + 32] = INFKEY;
        else if (lane < 16 && c == v)     cand[64 + lane] = INFKEY;
        __syncwarp();
        if (lane == r) picked = v;
        last = v;
    }
    cur = picked; thr = last; cnt = 0;
    __syncwarp();
}

__global__ __launch_bounds__(128) void knn_kernel() {
    __shared__ unsigned long long cand_s[4][80];
    const int warp = threadIdx.x >> 5, lane = threadIdx.x & 31;
    const int m = blockIdx.x * 4 + warp;
    unsigned long long* cand = cand_s[warp];

    const float4 Q = g_q4[m];
    unsigned long long cur = INFKEY, thr = INFKEY;
    int cnt = 0;

#pragma unroll 1
    for (int s = 0; s < Npts / 32; s++) {
        int idx = lane + 32 * s;
        float4 P = __ldg(&g_p4[idx]);
        // reference: qq - 2*(q@p.T) + pp, dot as XLA fma chain
        float dot = __fmaf_rn(Q.z, P.z, __fmaf_rn(Q.y, P.y, __fmul_rn(Q.x, P.x)));
        float d = __fadd_rn(__fsub_rn(Q.w, __fmul_rn(2.0f, dot)), P.w);
        unsigned ub = __float_as_uint(d);
        ub ^= (ub >> 31) ? 0xFFFFFFFFu : 0x80000000u;
        unsigned long long k = ((unsigned long long)ub << 32) | (unsigned)idx;
        bool pred = k < thr;
        unsigned bal = __ballot_sync(0xFFFFFFFFu, pred);
        if (pred) {
            int pos = cnt + __popc(bal & ((1u << lane) - 1u));
            cand[pos] = k;
        }
        cnt += __popc(bal);
        if (cnt >= 32) knn_merge(cand, lane, cur, thr, cnt);
    }
    if (cnt > 0) knn_merge(cand, lane, cur, thr, cnt);
    if (lane < 16) g_nidx[m * KNN + lane] = (int)(unsigned)(cur & 0xFFFFFFFFull);
}

// ---------------- gather + linear (feat @ W), stash h + partial BN sums ----------------
__global__ __launch_bounds__(128) void gemm_kernel(const float* __restrict__ x,
                                                   const float* __restrict__ W) {
    __shared__ float sW[FDIM * COUT];
    __shared__ float sF[KNN][FDIM + 1];
    const int m = blockIdx.x, t = threadIdx.x;

    for (int i = t; i < FDIM * COUT; i += 128) sW[i] = W[i];
    const float4 Q = g_q4[m];
    for (int e = t; e < KNN * FDIM; e += 128) {
        int r = e / FDIM, j = e - r * FDIM;
        int n = g_nidx[m * KNN + r];
        float v;
        if (j < 3) {
            float4 P = g_p4[n];
            v = (j == 0) ? __fsub_rn(P.x, Q.x) : (j == 1) ? __fsub_rn(P.y, Q.y)
                                                          : __fsub_rn(P.z, Q.z);
        } else {
            v = __ldg(&x[n * CIN + (j - 3)]);
        }
        sF[r][j] = v;
    }
    __syncthreads();

    float acc[KNN];
#pragma unroll
    for (int r = 0; r < KNN; r++) acc[r] = 0.0f;
#pragma unroll 1
    for (int j = 0; j < FDIM; j++) {
        float wv = sW[j * COUT + t];
#pragma unroll
        for (int r = 0; r < KNN; r++) acc[r] = fmaf(sF[r][j], wv, acc[r]);
    }
    float s1 = 0.0f, s2 = 0.0f;
#pragma unroll
    for (int r = 0; r < KNN; r++) {
        g_h[(m * KNN + r) * COUT + t] = acc[r];
        s1 += acc[r];
        s2 = fmaf(acc[r], acc[r], s2);
    }
    g_ps [m * COUT + t] = s1;
    g_pss[m * COUT + t] = s2;
}

// ---------------- deterministic BN stats reduction ----------------
__global__ __launch_bounds__(256) void stats_kernel() {
    __shared__ float s1[256], s2[256];
    const int c = blockIdx.x, t = threadIdx.x;
    float a = 0.0f, b = 0.0f;
    for (int m = t; m < Msamp; m += 256) {
        a += g_ps [m * COUT + c];
        b += g_pss[m * COUT + c];
    }
    s1[t] = a; s2[t] = b;
    __syncthreads();
    for (int o = 128; o; o >>= 1) {
        if (t < o) { s1[t] += s1[t + o]; s2[t] += s2[t + o]; }
        __syncthreads();
    }
    if (t == 0) {
        const float inv_n = 1.0f / (float)(Msamp * KNN);
        float mean = s1[0] * inv_n;
        float var  = fmaxf(s2[0] * inv_n - mean * mean, 0.0f);
        g_mean[c] = mean;
        g_rstd[c] = rsqrtf(var + BN_EPS);
    }
}

// ---------------- BN + ReLU + maxpool over k ----------------
__global__ __launch_bounds__(128) void final_kernel(const float* __restrict__ gamma,
                                                    const float* __restrict__ beta,
                                                    float* __restrict__ out_x,
                                                    float* __restrict__ out_no) {
    const int m = blockIdx.x, c = threadIdx.x;
    const float mean = g_mean[c], inv = g_rstd[c];
    const float gm = __ldg(&gamma[c]), bt = __ldg(&beta[c]);
    float mx = 0.0f;
#pragma unroll
    for (int r = 0; r < KNN; r++) {
        float h = g_h[(m * KNN + r) * COUT + c];
        float y = (h - mean) * inv * gm + bt;
        y = fmaxf(y, 0.0f);
        mx = fmaxf(mx, y);
    }
    out_x[m * COUT + c] = mx;
    if (out_no != nullptr && m == 0 && c == 0) *out_no = (float)Msamp;
}

// ---------------- launch ----------------
extern "C" void kernel_launch(void* const* d_in, const int* in_sizes, int n_in,
                              void* d_out, int out_size) {
    const float* p     = (const float*)d_in[0];
    const float* x     = (const float*)d_in[1];
    const float* W     = (const float*)d_in[3];
    const float* gamma = (const float*)d_in[4];
    const float* beta  = (const float*)d_in[5];
    float* out = (float*)d_out;

    const int np_elems = Msamp * 3;
    const int x_elems  = Msamp * COUT;

    float* np_dst = out;
    float* x_dst  = out + np_elems;
    float* no_dst = nullptr;
    if (out_size >= np_elems + x_elems + 1) {
        no_dst = out + np_elems + x_elems;
    } else if (out_size == x_elems) {
        float* scr; cudaGetSymbolAddress((void**)&scr, g_np_scratch);
        np_dst = scr;
        x_dst  = out;
    }

    pack_kernel     <<<(Npts + 255) / 256, 256>>>(p);
    fps_multi_kernel<<<FPS_CTAS, FPS_THREADS>>>(np_dst);
    knn_kernel      <<<Msamp / 4, 128>>>();
    gemm_kernel     <<<Msamp, 128>>>(x, W);
    stats_kernel    <<<COUT, 256>>>();
    final_kernel    <<<Msamp, 128>>>(gamma, beta, x_dst, no_dst);
}

// round 5
// speedup vs baseline: 5.2271x; 1.7316x over previous
#include <cuda_runtime.h>
#include <cstdint>

#define Npts   20000
#define Msamp  5000
#define KNN    16
#define CIN    64
#define COUT   128
#define FDIM   (3 + CIN)          // 67
#define BN_EPS 1e-5f

// FPS: one 8-CTA cluster, warp-granular DSMEM exchange
#define FPS_CTAS    8
#define FPS_THREADS 256
#define FPS_WARPS   (FPS_THREADS / 32)        // 8
#define FPS_SLOTS   (FPS_CTAS * FPS_WARPS)    // 64
#define FPS_PPC     (Npts / FPS_CTAS)         // 2500
#define FPS_PPT     10                         // ceil(2500/256)

// ---------------- device scratch (no allocs allowed) ----------------
__device__ float4 g_p4[Npts];          // x,y,z, |p|^2
__device__ float4 g_q4[Msamp];         // sampled q + |q|^2
__device__ int    g_nidx[Msamp * KNN];
__device__ float  g_h[Msamp * KNN * COUT];   // pre-BN activations
__device__ float  g_ps [Msamp * COUT];
__device__ float  g_pss[Msamp * COUT];
__device__ float  g_mean[COUT];
__device__ float  g_rstd[COUT];
__device__ float  g_np_scratch[Msamp * 3];

// ---------------- small PTX helpers ----------------
__device__ __forceinline__ uint32_t smem_u32(const void* p) {
    uint32_t a;
    asm("{ .reg .u64 t; cvta.to.shared.u64 t, %1; cvt.u32.u64 %0, t; }" : "=r"(a) : "l"(p));
    return a;
}
__device__ __forceinline__ uint32_t mapa_u32(uint32_t local_addr, uint32_t rank) {
    uint32_t r;
    asm("mapa.shared::cluster.u32 %0, %1, %2;" : "=r"(r) : "r"(local_addr), "r"(rank));
    return r;
}
__device__ __forceinline__ void st_async_u64(uint32_t raddr, unsigned long long v,
                                             uint32_t rmbar) {
    asm volatile("st.async.shared::cluster.mbarrier::complete_tx::bytes.b64 [%0], %1, [%2];"
                 :: "r"(raddr), "l"(v), "r"(rmbar) : "memory");
}
__device__ __forceinline__ void mbar_init(uint32_t mbar, uint32_t cnt) {
    asm volatile("mbarrier.init.shared.b64 [%0], %1;" :: "r"(mbar), "r"(cnt) : "memory");
}
__device__ __forceinline__ void mbar_expect_tx(uint32_t mbar, uint32_t bytes) {
    asm volatile("mbarrier.arrive.expect_tx.shared.b64 _, [%0], %1;"
                 :: "r"(mbar), "r"(bytes) : "memory");
}
__device__ __forceinline__ void mbar_wait_parity(uint32_t mbar, uint32_t ph) {
    uint32_t done = 0;
    while (!done) {
        asm volatile(
            "{\n\t.reg .pred p;\n\t"
            "mbarrier.try_wait.parity.acquire.cluster.shared::cta.b64 p, [%1], %2, 0x989680;\n\t"
            "selp.b32 %0, 1, 0, p;\n\t}"
            : "=r"(done) : "r"(mbar), "r"(ph) : "memory");
    }
}

// ---------------- pack: p [N,3] -> float4 with |p|^2 ----------------
__global__ void pack_kernel(const float* __restrict__ p) {
    int i = blockIdx.x * blockDim.x + threadIdx.x;
    if (i < Npts) {
        float x = p[3 * i], y = p[3 * i + 1], z = p[3 * i + 2];
        float pp = __fadd_rn(__fadd_rn(__fmul_rn(x, x), __fmul_rn(y, y)), __fmul_rn(z, z));
        g_p4[i] = make_float4(x, y, z, pp);
    }
}

// ---------------- FPS: 8-CTA cluster, st.async warp partials, mbarrier sync ----------------
// Arithmetic + argmax key law identical to the verified bit-exact versions.
__global__ void __cluster_dims__(FPS_CTAS, 1, 1) __launch_bounds__(FPS_THREADS, 1)
fps_cluster_kernel(float* __restrict__ out_np) {
    __shared__ unsigned long long s_slots[2][FPS_SLOTS];
    __shared__ unsigned long long s_mbar;

    const int t    = threadIdx.x;
    const int warp = t >> 5, lane = t & 31;
    uint32_t cta;
    asm("mov.u32 %0, %%cluster_ctarank;" : "=r"(cta));
    const int base = (int)cta * FPS_PPC;

    // register-resident slice
    float px[FPS_PPT], py[FPS_PPT], pz[FPS_PPT], dist[FPS_PPT];
    unsigned keylo[FPS_PPT];
    bool valid[FPS_PPT];
#pragma unroll
    for (int j = 0; j < FPS_PPT; j++) {
        int li = t + j * FPS_THREADS;
        valid[j] = (li < FPS_PPC);
        int gi = base + (valid[j] ? li : 0);
        float4 P = g_p4[gi];
        px[j] = P.x; py[j] = P.y; pz[j] = P.z;
        dist[j] = 1e10f;
        keylo[j] = (unsigned)(32767 - gi);
    }

    const uint32_t slot_base = smem_u32(&s_slots[0][0]);
    const uint32_t mbar_addr = smem_u32(&s_mbar);
    if (t == 0) mbar_init(mbar_addr, 1);

    // precompute remote addresses (lanes 0-7 are the senders)
    uint32_t r_slot0 = 0, r_slot1 = 0, r_mbar = 0;
    if (lane < FPS_CTAS) {
        uint32_t off = (uint32_t)(cta * FPS_WARPS + warp) * 8u;
        r_slot0 = mapa_u32(slot_base + off, lane);
        r_slot1 = mapa_u32(slot_base + FPS_SLOTS * 8u + off, lane);
        r_mbar  = mapa_u32(mbar_addr, lane);
    }

    // all mbarriers initialized before any st.async
    asm volatile("barrier.cluster.arrive.aligned;" ::: "memory");
    asm volatile("barrier.cluster.wait.aligned;" ::: "memory");

    float lx, ly, lz;
    {
        float4 P0 = g_p4[0];
        lx = P0.x; ly = P0.y; lz = P0.z;
        if (cta == 0 && t == 0) {
            out_np[0] = P0.x; out_np[1] = P0.y; out_np[2] = P0.z;
            g_q4[0] = P0;
        }
    }

    for (int i = 1; i < Msamp; i++) {
        // --- update dists, thread-local best key ---
        unsigned long long best = 0;
#pragma unroll
        for (int j = 0; j < FPS_PPT; j++) {
            float dx = __fsub_rn(px[j], lx);
            float dy = __fsub_rn(py[j], ly);
            float dz = __fsub_rn(pz[j], lz);
            float d  = __fadd_rn(__fadd_rn(__fmul_rn(dx, dx), __fmul_rn(dy, dy)),
                                 __fmul_rn(dz, dz));
            float nd = fminf(dist[j], d);
            dist[j] = nd;
            unsigned long long k =
                ((unsigned long long)__float_as_uint(nd) << 15) | keylo[j];
            if (valid[j] && k > best) best = k;
        }
        // --- warp xor-reduce: all lanes get warp max ---
#pragma unroll
        for (int off = 16; off; off >>= 1) {
            unsigned long long o = __shfl_xor_sync(0xFFFFFFFFu, best, off);
            if (o > best) best = o;
        }
        // --- broadcast warp partial to all 8 CTAs' slots ---
        const int buf = i & 1;
        if (lane < FPS_CTAS)
            st_async_u64(buf ? r_slot1 : r_slot0, best, r_mbar);
        if (t == 0)
            mbar_expect_tx(mbar_addr, FPS_SLOTS * 8u);

        // --- wait for all 64 partials, reduce redundantly per warp ---
        mbar_wait_parity(mbar_addr, (unsigned)((i & 1) ^ 1));
        unsigned long long v0 = s_slots[buf][lane];
        unsigned long long v1 = s_slots[buf][lane + 32];
        unsigned long long m = v0 > v1 ? v0 : v1;
#pragma unroll
        for (int off = 16; off; off >>= 1) {
            unsigned long long o = __shfl_xor_sync(0xFFFFFFFFu, m, off);
            if (o > m) m = o;
        }
        const int widx = 32767 - (int)(m & 0x7FFFull);
        float4 P = g_p4[widx];                 // L2 broadcast read
        lx = P.x; ly = P.y; lz = P.z;
        if (cta == 0 && t == 0) {
            out_np[3 * i] = P.x; out_np[3 * i + 1] = P.y; out_np[3 * i + 2] = P.z;
            g_q4[i] = P;
        }
    }
}

// ---------------- kNN: warp per query, threshold + ballot buffer ----------------
#define INFKEY 0xFFFFFFFFFFFFFFFFull

__device__ __forceinline__ void knn_merge(unsigned long long* cand, int lane,
                                          unsigned long long& cur,
                                          unsigned long long& thr, int& cnt) {
    if (lane < 16) cand[64 + lane] = cur;
#pragma unroll
    for (int s = lane; s < 64; s += 32) if (s >= cnt) cand[s] = INFKEY;
    __syncwarp();
    unsigned long long picked = INFKEY, last = INFKEY;
#pragma unroll 1
    for (int r = 0; r < 16; r++) {
        unsigned long long a = cand[lane];
        unsigned long long b = cand[lane + 32];
        unsigned long long c = (lane < 16) ? cand[64 + lane] : INFKEY;
        unsigned long long v = a < b ? a : b;
        v = v < c ? v : c;
#pragma unroll
        for (int off = 16; off; off >>= 1) {
            unsigned long long o = __shfl_down_sync(0xFFFFFFFFu, v, off);
            if (o < v) v = o;
        }
        v = __shfl_sync(0xFFFFFFFFu, v, 0);
        if (a == v)                       cand[lane]      = INFKEY;
        else if (b == v)                  cand[lane + 32] = INFKEY;
        else if (lane < 16 && c == v)     cand[64 + lane] = INFKEY;
        __syncwarp();
        if (lane == r) picked = v;
        last = v;
    }
    cur = picked; thr = last; cnt = 0;
    __syncwarp();
}

__global__ __launch_bounds__(128) void knn_kernel() {
    __shared__ unsigned long long cand_s[4][80];
    const int warp = threadIdx.x >> 5, lane = threadIdx.x & 31;
    const int m = blockIdx.x * 4 + warp;
    unsigned long long* cand = cand_s[warp];

    const float4 Q = g_q4[m];
    unsigned long long cur = INFKEY, thr = INFKEY;
    int cnt = 0;

#pragma unroll 1
    for (int s = 0; s < Npts / 32; s++) {
        int idx = lane + 32 * s;
        float4 P = __ldg(&g_p4[idx]);
        // reference: qq - 2*(q@p.T) + pp, dot as XLA fma chain
        float dot = __fmaf_rn(Q.z, P.z, __fmaf_rn(Q.y, P.y, __fmul_rn(Q.x, P.x)));
        float d = __fadd_rn(__fsub_rn(Q.w, __fmul_rn(2.0f, dot)), P.w);
        unsigned ub = __float_as_uint(d);
        ub ^= (ub >> 31) ? 0xFFFFFFFFu : 0x80000000u;
        unsigned long long k = ((unsigned long long)ub << 32) | (unsigned)idx;
        bool pred = k < thr;
        unsigned bal = __ballot_sync(0xFFFFFFFFu, pred);
        if (pred) {
            int pos = cnt + __popc(bal & ((1u << lane) - 1u));
            cand[pos] = k;
        }
        cnt += __popc(bal);
        if (cnt >= 32) knn_merge(cand, lane, cur, thr, cnt);
    }
    if (cnt > 0) knn_merge(cand, lane, cur, thr, cnt);
    if (lane < 16) g_nidx[m * KNN + lane] = (int)(unsigned)(cur & 0xFFFFFFFFull);
}

// ---------------- gather + linear (feat @ W), stash h + partial BN sums ----------------
__global__ __launch_bounds__(128) void gemm_kernel(const float* __restrict__ x,
                                                   const float* __restrict__ W) {
    __shared__ float sW[FDIM * COUT];
    __shared__ float sF[KNN][FDIM + 1];
    const int m = blockIdx.x, t = threadIdx.x;

    for (int i = t; i < FDIM * COUT; i += 128) sW[i] = W[i];
    const float4 Q = g_q4[m];
    for (int e = t; e < KNN * FDIM; e += 128) {
        int r = e / FDIM, j = e - r * FDIM;
        int n = g_nidx[m * KNN + r];
        float v;
        if (j < 3) {
            float4 P = g_p4[n];
            v = (j == 0) ? __fsub_rn(P.x, Q.x) : (j == 1) ? __fsub_rn(P.y, Q.y)
                                                          : __fsub_rn(P.z, Q.z);
        } else {
            v = __ldg(&x[n * CIN + (j - 3)]);
        }
        sF[r][j] = v;
    }
    __syncthreads();

    float acc[KNN];
#pragma unroll
    for (int r = 0; r < KNN; r++) acc[r] = 0.0f;
#pragma unroll 1
    for (int j = 0; j < FDIM; j++) {
        float wv = sW[j * COUT + t];
#pragma unroll
        for (int r = 0; r < KNN; r++) acc[r] = fmaf(sF[r][j], wv, acc[r]);
    }
    float s1 = 0.0f, s2 = 0.0f;
#pragma unroll
    for (int r = 0; r < KNN; r++) {
        g_h[(m * KNN + r) * COUT + t] = acc[r];
        s1 += acc[r];
        s2 = fmaf(acc[r], acc[r], s2);
    }
    g_ps [m * COUT + t] = s1;
    g_pss[m * COUT + t] = s2;
}

// ---------------- deterministic BN stats reduction ----------------
__global__ __launch_bounds__(256) void stats_kernel() {
    __shared__ float s1[256], s2[256];
    const int c = blockIdx.x, t = threadIdx.x;
    float a = 0.0f, b = 0.0f;
    for (int m = t; m < Msamp; m += 256) {
        a += g_ps [m * COUT + c];
        b += g_pss[m * COUT + c];
    }
    s1[t] = a; s2[t] = b;
    __syncthreads();
    for (int o = 128; o; o >>= 1) {
        if (t < o) { s1[t] += s1[t + o]; s2[t] += s2[t + o]; }
        __syncthreads();
    }
    if (t == 0) {
        const float inv_n = 1.0f / (float)(Msamp * KNN);
        float mean = s1[0] * inv_n;
        float var  = fmaxf(s2[0] * inv_n - mean * mean, 0.0f);
        g_mean[c] = mean;
        g_rstd[c] = rsqrtf(var + BN_EPS);
    }
}

// ---------------- BN + ReLU + maxpool over k ----------------
__global__ __launch_bounds__(128) void final_kernel(const float* __restrict__ gamma,
                                                    const float* __restrict__ beta,
                                                    float* __restrict__ out_x,
                                                    float* __restrict__ out_no) {
    const int m = blockIdx.x, c = threadIdx.x;
    const float mean = g_mean[c], inv = g_rstd[c];
    const float gm = __ldg(&gamma[c]), bt = __ldg(&beta[c]);
    float mx = 0.0f;
#pragma unroll
    for (int r = 0; r < KNN; r++) {
        float h = g_h[(m * KNN + r) * COUT + c];
        float y = (h - mean) * inv * gm + bt;
        y = fmaxf(y, 0.0f);
        mx = fmaxf(mx, y);
    }
    out_x[m * COUT + c] = mx;
    if (out_no != nullptr && m == 0 && c == 0) *out_no = (float)Msamp;
}

// ---------------- launch ----------------
extern "C" void kernel_launch(void* const* d_in, const int* in_sizes, int n_in,
                              void* d_out, int out_size) {
    const float* p     = (const float*)d_in[0];
    const float* x     = (const float*)d_in[1];
    const float* W     = (const float*)d_in[3];
    const float* gamma = (const float*)d_in[4];
    const float* beta  = (const float*)d_in[5];
    float* out = (float*)d_out;

    const int np_elems = Msamp * 3;
    const int x_elems  = Msamp * COUT;

    float* np_dst = out;
    float* x_dst  = out + np_elems;
    float* no_dst = nullptr;
    if (out_size >= np_elems + x_elems + 1) {
        no_dst = out + np_elems + x_elems;
    } else if (out_size == x_elems) {
        float* scr; cudaGetSymbolAddress((void**)&scr, g_np_scratch);
        np_dst = scr;
        x_dst  = out;
    }

    pack_kernel       <<<(Npts + 255) / 256, 256>>>(p);
    fps_cluster_kernel<<<FPS_CTAS, FPS_THREADS>>>(np_dst);
    knn_kernel        <<<Msamp / 4, 128>>>();
    gemm_kernel       <<<Msamp, 128>>>(x, W);
    stats_kernel      <<<COUT, 256>>>();
    final_kernel      <<<Msamp, 128>>>(gamma, beta, x_dst, no_dst);
}

// round 6
// speedup vs baseline: 5.6059x; 1.0725x over previous
#include <cuda_runtime.h>
#include <cstdint>

#define Npts   20000
#define Msamp  5000
#define KNN    16
#define CIN    64
#define COUT   128
#define FDIM   (3 + CIN)          // 67
#define BN_EPS 1e-5f

// FPS: one 8-CTA cluster, warp-granular DSMEM exchange
#define FPS_CTAS    8
#define FPS_THREADS 256
#define FPS_WARPS   (FPS_THREADS / 32)        // 8
#define FPS_SLOTS   (FPS_CTAS * FPS_WARPS)    // 64
#define FPS_PPC     (Npts / FPS_CTAS)         // 2500
#define FPS_PPT     10                         // ceil(2500/256)
#define SLOT_BYTES  24                         // key(8) + xy(8) + zw(8)

// ---------------- device scratch (no allocs allowed) ----------------
__device__ float4 g_p4[Npts];          // x,y,z, |p|^2
__device__ float4 g_q4[Msamp];         // sampled q + |q|^2
__device__ int    g_nidx[Msamp * KNN];
__device__ float  g_h[Msamp * KNN * COUT];   // pre-BN activations
__device__ float  g_ps [Msamp * COUT];
__device__ float  g_pss[Msamp * COUT];
__device__ float  g_mean[COUT];
__device__ float  g_rstd[COUT];
__device__ float  g_np_scratch[Msamp * 3];

// ---------------- small PTX helpers ----------------
__device__ __forceinline__ uint32_t smem_u32(const void* p) {
    uint32_t a;
    asm("{ .reg .u64 t; cvta.to.shared.u64 t, %1; cvt.u32.u64 %0, t; }" : "=r"(a) : "l"(p));
    return a;
}
__device__ __forceinline__ uint32_t mapa_u32(uint32_t local_addr, uint32_t rank) {
    uint32_t r;
    asm("mapa.shared::cluster.u32 %0, %1, %2;" : "=r"(r) : "r"(local_addr), "r"(rank));
    return r;
}
__device__ __forceinline__ void st_async_u64(uint32_t raddr, unsigned long long v,
                                             uint32_t rmbar) {
    asm volatile("st.async.shared::cluster.mbarrier::complete_tx::bytes.b64 [%0], %1, [%2];"
                 :: "r"(raddr), "l"(v), "r"(rmbar) : "memory");
}
__device__ __forceinline__ void mbar_init(uint32_t mbar, uint32_t cnt) {
    asm volatile("mbarrier.init.shared.b64 [%0], %1;" :: "r"(mbar), "r"(cnt) : "memory");
}
__device__ __forceinline__ void mbar_expect_tx(uint32_t mbar, uint32_t bytes) {
    asm volatile("mbarrier.arrive.expect_tx.shared.b64 _, [%0], %1;"
                 :: "r"(mbar), "r"(bytes) : "memory");
}
__device__ __forceinline__ void mbar_wait_parity(uint32_t mbar, uint32_t ph) {
    uint32_t done = 0;
    while (!done) {
        asm volatile(
            "{\n\t.reg .pred p;\n\t"
            "mbarrier.try_wait.parity.acquire.cluster.shared::cta.b64 p, [%1], %2, 0x989680;\n\t"
            "selp.b32 %0, 1, 0, p;\n\t}"
            : "=r"(done) : "r"(mbar), "r"(ph) : "memory");
    }
}
__device__ __forceinline__ unsigned long long pack2f(float a, float b) {
    return ((unsigned long long)__float_as_uint(b) << 32) | __float_as_uint(a);
}

// ---------------- pack: p [N,3] -> float4 with |p|^2 ----------------
__global__ void pack_kernel(const float* __restrict__ p) {
    int i = blockIdx.x * blockDim.x + threadIdx.x;
    if (i < Npts) {
        float x = p[3 * i], y = p[3 * i + 1], z = p[3 * i + 2];
        float pp = __fadd_rn(__fadd_rn(__fmul_rn(x, x), __fmul_rn(y, y)), __fmul_rn(z, z));
        g_p4[i] = make_float4(x, y, z, pp);
    }
}

// ---------------- FPS: 8-CTA cluster, coords-in-slot, redux reduces ----------------
// Distance arithmetic + argmax key law identical to the verified bit-exact versions.
__global__ void __cluster_dims__(FPS_CTAS, 1, 1) __launch_bounds__(FPS_THREADS, 1)
fps_cluster_kernel(float* __restrict__ out_np) {
    __shared__ unsigned long long s_slots[2][FPS_SLOTS * 3];   // key, xy, zw per slot
    __shared__ unsigned long long s_mbar[2];

    const int t    = threadIdx.x;
    const int warp = t >> 5, lane = t & 31;
    uint32_t cta;
    asm("mov.u32 %0, %%cluster_ctarank;" : "=r"(cta));
    const int base = (int)cta * FPS_PPC;

    // register-resident slice
    float px[FPS_PPT], py[FPS_PPT], pz[FPS_PPT], pw[FPS_PPT], dist[FPS_PPT];
    unsigned gi[FPS_PPT];
    bool valid[FPS_PPT];
#pragma unroll
    for (int j = 0; j < FPS_PPT; j++) {
        int li = t + j * FPS_THREADS;
        valid[j] = (li < FPS_PPC);
        int g = base + (valid[j] ? li : 0);
        float4 P = g_p4[g];
        px[j] = P.x; py[j] = P.y; pz[j] = P.z; pw[j] = P.w;
        dist[j] = 1e10f;
        gi[j] = (unsigned)g;
    }

    const uint32_t slot_base = smem_u32(&s_slots[0][0]);
    const uint32_t mbar_base = smem_u32(&s_mbar[0]);
    if (t == 0) { mbar_init(mbar_base, 1); mbar_init(mbar_base + 8, 1); }

    // remote addresses for senders (lanes 0-7 -> one CTA each)
    uint32_t r_slot[2] = {0, 0}, r_mbar[2] = {0, 0};
    if (lane < FPS_CTAS) {
        uint32_t soff = (uint32_t)(cta * FPS_WARPS + warp) * SLOT_BYTES;
        r_slot[0] = mapa_u32(slot_base + soff, lane);
        r_slot[1] = mapa_u32(slot_base + FPS_SLOTS * SLOT_BYTES + soff, lane);
        r_mbar[0] = mapa_u32(mbar_base, lane);
        r_mbar[1] = mapa_u32(mbar_base + 8, lane);
    }

    asm volatile("barrier.cluster.arrive.aligned;" ::: "memory");
    asm volatile("barrier.cluster.wait.aligned;" ::: "memory");

    float lx, ly, lz;
    {
        float4 P0 = g_p4[0];
        lx = P0.x; ly = P0.y; lz = P0.z;
        if (cta == 0 && t == 0) {
            out_np[0] = P0.x; out_np[1] = P0.y; out_np[2] = P0.z;
            g_q4[0] = P0;
        }
    }

    unsigned ph0 = 0, ph1 = 0;   // per-mbar phase parity

    for (int i = 1; i < Msamp; i++) {
        // --- update dists, per-thread argmax (uint order == float order, d>=0) ---
        unsigned bd = 0, bi = 0x7FFFFFFFu;
        float bx = 0.f, by = 0.f, bz = 0.f, bw = 0.f;
#pragma unroll
        for (int j = 0; j < FPS_PPT; j++) {
            float dx = __fsub_rn(px[j], lx);
            float dy = __fsub_rn(py[j], ly);
            float dz = __fsub_rn(pz[j], lz);
            float d  = __fadd_rn(__fadd_rn(__fmul_rn(dx, dx), __fmul_rn(dy, dy)),
                                 __fmul_rn(dz, dz));
            float nd = fminf(dist[j], d);
            dist[j] = nd;
            unsigned db = __float_as_uint(nd);
            if (valid[j] && db > bd) {            // strict > keeps lowest idx in-thread
                bd = db; bi = gi[j];
                bx = px[j]; by = py[j]; bz = pz[j]; bw = pw[j];
            }
        }
        // --- warp argmax via redux: max dist, tie -> min global index ---
        unsigned dmax = __reduce_max_sync(0xFFFFFFFFu, bd);
        bool cand = (bd == dmax);
        unsigned idxmin = __reduce_min_sync(0xFFFFFFFFu, cand ? bi : 0xFFFFFFFFu);
        unsigned long long key =
            ((unsigned long long)dmax << 15) | (unsigned)((32767u - idxmin) & 0x7FFFu);

        const int buf = i & 1;
        // the winning lane (holder of dmax & idxmin) broadcasts coords through shfl
        unsigned src_ballot = __ballot_sync(0xFFFFFFFFu, cand && bi == idxmin);
        int src = __ffs(src_ballot) - 1;
        float wx = __shfl_sync(0xFFFFFFFFu, bx, src);
        float wy = __shfl_sync(0xFFFFFFFFu, by, src);
        float wz = __shfl_sync(0xFFFFFFFFu, bz, src);
        float ww = __shfl_sync(0xFFFFFFFFu, bw, src);

        if (lane < FPS_CTAS) {
            uint32_t rs = r_slot[buf], rm = r_mbar[buf];
            st_async_u64(rs,      key,            rm);
            st_async_u64(rs + 8,  pack2f(wx, wy), rm);
            st_async_u64(rs + 16, pack2f(wz, ww), rm);
        }
        if (t == 0)
            mbar_expect_tx(mbar_base + 8u * (unsigned)buf,
                           FPS_SLOTS * SLOT_BYTES);

        // --- wait for all 64 slot triplets ---
        unsigned myph = buf ? ph1 : ph0;
        mbar_wait_parity(mbar_base + 8u * (unsigned)buf, myph);
        if (buf) ph1 ^= 1; else ph0 ^= 1;

        // --- cross-slot argmax on keys (redux on split fields) ---
        unsigned long long v0 = s_slots[buf][lane * 3];
        unsigned long long v1 = s_slots[buf][(lane + 32) * 3];
        unsigned d0 = (unsigned)(v0 >> 15), d1 = (unsigned)(v1 >> 15);
        unsigned dg = __reduce_max_sync(0xFFFFFFFFu, d0 > d1 ? d0 : d1);
        unsigned l = 0;
        if (d0 == dg) l = (unsigned)v0 & 0x7FFFu;
        if (d1 == dg) { unsigned l1 = (unsigned)v1 & 0x7FFFu; if (l1 > l) l = l1; }
        unsigned lg = __reduce_max_sync(0xFFFFFFFFu, l);
        unsigned long long wkey = ((unsigned long long)dg << 15) | lg;

        int sl;
        unsigned b0 = __ballot_sync(0xFFFFFFFFu, v0 == wkey);
        if (b0) sl = __ffs(b0) - 1;
        else {
            unsigned b1 = __ballot_sync(0xFFFFFFFFu, v1 == wkey);
            sl = 32 + __ffs(b1) - 1;
        }
        unsigned long long wxy = s_slots[buf][sl * 3 + 1];
        unsigned long long wzw = s_slots[buf][sl * 3 + 2];
        lx = __uint_as_float((unsigned)wxy);
        ly = __uint_as_float((unsigned)(wxy >> 32));
        lz = __uint_as_float((unsigned)wzw);
        if (cta == 0 && t == 0) {
            float w = __uint_as_float((unsigned)(wzw >> 32));
            out_np[3 * i] = lx; out_np[3 * i + 1] = ly; out_np[3 * i + 2] = lz;
            g_q4[i] = make_float4(lx, ly, lz, w);
        }
    }
}

// ---------------- kNN: warp per query, threshold + ballot buffer ----------------
#define INFKEY 0xFFFFFFFFFFFFFFFFull

__device__ __forceinline__ void knn_merge(unsigned long long* cand, int lane,
                                          unsigned long long& cur,
                                          unsigned long long& thr, int& cnt) {
    if (lane < 16) cand[64 + lane] = cur;
#pragma unroll
    for (int s = lane; s < 64; s += 32) if (s >= cnt) cand[s] = INFKEY;
    __syncwarp();
    unsigned long long picked = INFKEY, last = INFKEY;
#pragma unroll 1
    for (int r = 0; r < 16; r++) {
        unsigned long long a = cand[lane];
        unsigned long long b = cand[lane + 32];
        unsigned long long c = (lane < 16) ? cand[64 + lane] : INFKEY;
        unsigned long long v = a < b ? a : b;
        v = v < c ? v : c;
#pragma unroll
        for (int off = 16; off; off >>= 1) {
            unsigned long long o = __shfl_down_sync(0xFFFFFFFFu, v, off);
            if (o < v) v = o;
        }
        v = __shfl_sync(0xFFFFFFFFu, v, 0);
        if (a == v)                       cand[lane]      = INFKEY;
        else if (b == v)                  cand[lane + 32] = INFKEY;
        else if (lane < 16 && c == v)     cand[64 + lane] = INFKEY;
        __syncwarp();
        if (lane == r) picked = v;
        last = v;
    }
    cur = picked; thr = last; cnt = 0;
    __syncwarp();
}

__global__ __launch_bounds__(128) void knn_kernel() {
    __shared__ unsigned long long cand_s[4][80];
    const int warp = threadIdx.x >> 5, lane = threadIdx.x & 31;
    const int m = blockIdx.x * 4 + warp;
    unsigned long long* cand = cand_s[warp];

    const float4 Q = g_q4[m];
    unsigned long long cur = INFKEY, thr = INFKEY;
    int cnt = 0;

#pragma unroll 1
    for (int s = 0; s < Npts / 32; s++) {
        int idx = lane + 32 * s;
        float4 P = __ldg(&g_p4[idx]);
        // reference: qq - 2*(q@p.T) + pp, dot as XLA fma chain
        float dot = __fmaf_rn(Q.z, P.z, __fmaf_rn(Q.y, P.y, __fmul_rn(Q.x, P.x)));
        float d = __fadd_rn(__fsub_rn(Q.w, __fmul_rn(2.0f, dot)), P.w);
        unsigned ub = __float_as_uint(d);
        ub ^= (ub >> 31) ? 0xFFFFFFFFu : 0x80000000u;
        unsigned long long k = ((unsigned long long)ub << 32) | (unsigned)idx;
        bool pred = k < thr;
        unsigned bal = __ballot_sync(0xFFFFFFFFu, pred);
        if (pred) {
            int pos = cnt + __popc(bal & ((1u << lane) - 1u));
            cand[pos] = k;
        }
        cnt += __popc(bal);
        if (cnt >= 32) knn_merge(cand, lane, cur, thr, cnt);
    }
    if (cnt > 0) knn_merge(cand, lane, cur, thr, cnt);
    if (lane < 16) g_nidx[m * KNN + lane] = (int)(unsigned)(cur & 0xFFFFFFFFull);
}

// ---------------- gather + linear (feat @ W), stash h + partial BN sums ----------------
__global__ __launch_bounds__(128) void gemm_kernel(const float* __restrict__ x,
                                                   const float* __restrict__ W) {
    __shared__ float sW[FDIM * COUT];
    __shared__ float sF[KNN][FDIM + 1];
    const int m = blockIdx.x, t = threadIdx.x;

    for (int i = t; i < FDIM * COUT; i += 128) sW[i] = W[i];
    const float4 Q = g_q4[m];
    for (int e = t; e < KNN * FDIM; e += 128) {
        int r = e / FDIM, j = e - r * FDIM;
        int n = g_nidx[m * KNN + r];
        float v;
        if (j < 3) {
            float4 P = g_p4[n];
            v = (j == 0) ? __fsub_rn(P.x, Q.x) : (j == 1) ? __fsub_rn(P.y, Q.y)
                                                          : __fsub_rn(P.z, Q.z);
        } else {
            v = __ldg(&x[n * CIN + (j - 3)]);
        }
        sF[r][j] = v;
    }
    __syncthreads();

    float acc[KNN];
#pragma unroll
    for (int r = 0; r < KNN; r++) acc[r] = 0.0f;
#pragma unroll 1
    for (int j = 0; j < FDIM; j++) {
        float wv = sW[j * COUT + t];
#pragma unroll
        for (int r = 0; r < KNN; r++) acc[r] = fmaf(sF[r][j], wv, acc[r]);
    }
    float s1 = 0.0f, s2 = 0.0f;
#pragma unroll
    for (int r = 0; r < KNN; r++) {
        g_h[(m * KNN + r) * COUT + t] = acc[r];
        s1 += acc[r];
        s2 = fmaf(acc[r], acc[r], s2);
    }
    g_ps [m * COUT + t] = s1;
    g_pss[m * COUT + t] = s2;
}

// ---------------- deterministic BN stats reduction ----------------
__global__ __launch_bounds__(256) void stats_kernel() {
    __shared__ float s1[256], s2[256];
    const int c = blockIdx.x, t = threadIdx.x;
    float a = 0.0f, b = 0.0f;
    for (int m = t; m < Msamp; m += 256) {
        a += g_ps [m * COUT + c];
        b += g_pss[m * COUT + c];
    }
    s1[t] = a; s2[t] = b;
    __syncthreads();
    for (int o = 128; o; o >>= 1) {
        if (t < o) { s1[t] += s1[t + o]; s2[t] += s2[t + o]; }
        __syncthreads();
    }
    if (t == 0) {
        const float inv_n = 1.0f / (float)(Msamp * KNN);
        float mean = s1[0] * inv_n;
        float var  = fmaxf(s2[0] * inv_n - mean * mean, 0.0f);
        g_mean[c] = mean;
        g_rstd[c] = rsqrtf(var + BN_EPS);
    }
}

// ---------------- BN + ReLU + maxpool over k ----------------
__global__ __launch_bounds__(128) void final_kernel(const float* __restrict__ gamma,
                                                    const float* __restrict__ beta,
                                                    float* __restrict__ out_x,
                                                    float* __restrict__ out_no) {
    const int m = blockIdx.x, c = threadIdx.x;
    const float mean = g_mean[c], inv = g_rstd[c];
    const float gm = __ldg(&gamma[c]), bt = __ldg(&beta[c]);
    float mx = 0.0f;
#pragma unroll
    for (int r = 0; r < KNN; r++) {
        float h = g_h[(m * KNN + r) * COUT + c];
        float y = (h - mean) * inv * gm + bt;
        y = fmaxf(y, 0.0f);
        mx = fmaxf(mx, y);
    }
    out_x[m * COUT + c] = mx;
    if (out_no != nullptr && m == 0 && c == 0) *out_no = (float)Msamp;
}

// ---------------- launch ----------------
extern "C" void kernel_launch(void* const* d_in, const int* in_sizes, int n_in,
                              void* d_out, int out_size) {
    const float* p     = (const float*)d_in[0];
    const float* x     = (const float*)d_in[1];
    const float* W     = (const float*)d_in[3];
    const float* gamma = (const float*)d_in[4];
    const float* beta  = (const float*)d_in[5];
    float* out = (float*)d_out;

    const int np_elems = Msamp * 3;
    const int x_elems  = Msamp * COUT;

    float* np_dst = out;
    float* x_dst  = out + np_elems;
    float* no_dst = nullptr;
    if (out_size >= np_elems + x_elems + 1) {
        no_dst = out + np_elems + x_elems;
    } else if (out_size == x_elems) {
        float* scr; cudaGetSymbolAddress((void**)&scr, g_np_scratch);
        np_dst = scr;
        x_dst  = out;
    }

    pack_kernel       <<<(Npts + 255) / 256, 256>>>(p);
    fps_cluster_kernel<<<FPS_CTAS, FPS_THREADS>>>(np_dst);
    knn_kernel        <<<Msamp / 4, 128>>>();
    gemm_kernel       <<<Msamp, 128>>>(x, W);
    stats_kernel      <<<COUT, 256>>>();
    final_kernel      <<<Msamp, 128>>>(gamma, beta, x_dst, no_dst);
}